// round 5
// baseline (speedup 1.0000x reference)
#include <cuda_runtime.h>
#include <math.h>

#define POOLK 7
#define HH 50
#define WW 50
#define CC 512
#define NROIS 300
#define NPOS (HH * WW)
#define NBINS (POOLK * POOLK)
#define NWORK (NROIS * NBINS)   // 14700 warps of work

// Device-global scratch (no allocations allowed).
__device__ float g_fmax[NPOS];  // 10 KB channel-max map, L2-resident

// ---------------------------------------------------------------------------
// Kernel 1: fmax[h][w] = max_c feature_maps[h][w][c]
// 128 threads per spatial position (1 float4 each) -> 320K threads, high occ.
// ---------------------------------------------------------------------------
__global__ void __launch_bounds__(256) fmax_kernel(const float* __restrict__ fm) {
    const int gid = blockIdx.x * 256 + threadIdx.x;
    const int pos = gid >> 7;               // grid sized exactly
    const int t = threadIdx.x & 127;
    const int grp = threadIdx.x >> 7;
    const int w4 = (threadIdx.x >> 5) & 3;
    const int lane = threadIdx.x & 31;

    const float4 v = reinterpret_cast<const float4*>(fm + (size_t)pos * CC)[t];
    float m = fmaxf(fmaxf(v.x, v.y), fmaxf(v.z, v.w));
#pragma unroll
    for (int o = 16; o; o >>= 1)
        m = fmaxf(m, __shfl_xor_sync(0xffffffffu, m, o));

    __shared__ float part[2][4];
    if (lane == 0) part[grp][w4] = m;
    __syncthreads();
    if (t == 0)
        g_fmax[pos] = fmaxf(fmaxf(part[grp][0], part[grp][1]),
                            fmaxf(part[grp][2], part[grp][3]));
}

// ---------------------------------------------------------------------------
// Kernel 2: one WARP per (roi, bin). No shared memory, no block barriers, no
// runtime division. Bin region is provably <= 5x5; lanes map statically to a
// 5x5 grid (const div/mod by 5), gather from L2-hot g_fmax, shfl-reduce so
// every lane holds the bin max in a register, then 4 unrolled STG.128 per lane
// write the 512-channel broadcast (coalesced 512B per warp instruction).
// ---------------------------------------------------------------------------
__global__ void __launch_bounds__(256) roi_kernel(const float* __restrict__ rois,
                                                  float* __restrict__ out) {
    const int gw = blockIdx.x * 8 + (threadIdx.x >> 5);  // global warp id
    if (gw >= NWORK) return;
    const int lane = threadIdx.x & 31;

    const int roi = gw / NBINS;              // const divisor -> mul/shift
    const int bin = gw - roi * NBINS;
    const int ph = bin / POOLK;              // const divisor
    const int pw = bin - ph * POOLK;

    const float* r = rois + roi * 5;
    // truncation matches astype(int32) for nonneg; *0.0625f exact (== /16)
    const int x1 = (int)(__ldg(r + 1) * 0.0625f);
    const int y1 = (int)(__ldg(r + 2) * 0.0625f);
    const int x2 = (int)(__ldg(r + 3) * 0.0625f);
    const int y2 = (int)(__ldg(r + 4) * 0.0625f);
    const int rh = y2 - y1 + 1;
    const int rw = x2 - x1 + 1;

    const int hs = min(max(y1 + (ph * rh) / POOLK, 0), HH);
    const int he = min(max(y1 + ((ph + 1) * rh + POOLK - 1) / POOLK, 0), HH);
    const int ws = min(max(x1 + (pw * rw) / POOLK, 0), WW);
    const int we = min(max(x1 + ((pw + 1) * rw + POOLK - 1) / POOLK, 0), WW);
    const int nh = he - hs;
    const int nw = we - ws;

    // Static 5x5 lane map (bin span <= 5 in each dim since rw,rh <= 26).
    const int dh = lane / 5;                 // const divisor
    const int dw = lane - dh * 5;

    float m = -INFINITY;
    if (dh < nh && dw < nw)
        m = __ldg(g_fmax + (hs + dh) * WW + (ws + dw));
#pragma unroll
    for (int o = 16; o; o >>= 1)
        m = fmaxf(m, __shfl_xor_sync(0xffffffffu, m, o));

    // Broadcast-store 512 floats = 128 float4; 4 per lane, fully unrolled.
    float4* o4 = reinterpret_cast<float4*>(out) + (size_t)gw * (CC / 4);
    const float4 vv = make_float4(m, m, m, m);
#pragma unroll
    for (int i = 0; i < 4; ++i)
        o4[lane + 32 * i] = vv;
}

extern "C" void kernel_launch(void* const* d_in, const int* in_sizes, int n_in,
                              void* d_out, int out_size) {
    const float* rois = (const float*)d_in[0];
    const float* fm = (const float*)d_in[1];
    if (n_in >= 2 && in_sizes[0] > in_sizes[1]) {
        rois = (const float*)d_in[1];
        fm = (const float*)d_in[0];
    }
    float* out = (float*)d_out;

    fmax_kernel<<<(NPOS * 128) / 256, 256>>>(fm);          // 1250 blocks
    roi_kernel<<<(NWORK + 7) / 8, 256>>>(rois, out);       // 1838 blocks
}

// round 6
// speedup vs baseline: 1.2965x; 1.2965x over previous
#include <cuda_runtime.h>
#include <math.h>
#include <stdint.h>

#define POOLK 7
#define HH 50
#define WW 50
#define CC 512
#define NROIS 300
#define NPOS (HH * WW)

// Device-global scratch (no allocations allowed).
__device__ float g_fmax[NPOS];  // 10 KB channel-max map, L2-resident

__device__ __forceinline__ uint32_t smem_u32(const void* p) {
    uint32_t a;
    asm("{ .reg .u64 t; cvta.to.shared.u64 t, %1; cvt.u32.u64 %0, t; }"
        : "=r"(a) : "l"(p));
    return a;
}

// ---------------------------------------------------------------------------
// Kernel 1: fmax[h][w] = max_c feature_maps[h][w][c]
// 128 threads per spatial position (1 float4 each) -> 320K threads, high occ.
// ---------------------------------------------------------------------------
__global__ void __launch_bounds__(256) fmax_kernel(const float* __restrict__ fm) {
    const int gid = blockIdx.x * 256 + threadIdx.x;
    const int pos = gid >> 7;               // grid sized exactly
    const int t = threadIdx.x & 127;
    const int grp = threadIdx.x >> 7;
    const int w4 = (threadIdx.x >> 5) & 3;
    const int lane = threadIdx.x & 31;

    const float4 v = reinterpret_cast<const float4*>(fm + (size_t)pos * CC)[t];
    float m = fmaxf(fmaxf(v.x, v.y), fmaxf(v.z, v.w));
#pragma unroll
    for (int o = 16; o; o >>= 1)
        m = fmaxf(m, __shfl_xor_sync(0xffffffffu, m, o));

    __shared__ float part[2][4];
    if (lane == 0) part[grp][w4] = m;
    __syncthreads();
    if (t == 0)
        g_fmax[pos] = fmaxf(fmaxf(part[grp][0], part[grp][1]),
                            fmaxf(part[grp][2], part[grp][3]));
}

// ---------------------------------------------------------------------------
// Kernel 2: one block per (roi, ph). Warps 0..6 compute bin maxima for pw=0..6
// (lane-strided gather over the <= ~25-element bin region of L2-hot g_fmax,
// shfl-reduce leaves the max in every lane), then each warp fills its 2 KB
// broadcast slice of a 14 KB shared tile via STS.128. One elected thread then
// issues a single cp.async.bulk store of the whole 14336-byte tile -> the
// 30 MB output stream bypasses the per-thread STG path entirely.
// ---------------------------------------------------------------------------
__global__ void __launch_bounds__(256) roi_kernel(const float* __restrict__ rois,
                                                  float* __restrict__ out) {
    __shared__ __align__(16) float stile[POOLK * CC];  // 14336 B

    const int roi = blockIdx.x / POOLK;
    const int ph = blockIdx.x - roi * POOLK;

    const float* r = rois + roi * 5;
    // truncation matches astype(int32) for nonneg; *0.0625f exact (== /16)
    const int x1 = (int)(__ldg(r + 1) * 0.0625f);
    const int y1 = (int)(__ldg(r + 2) * 0.0625f);
    const int x2 = (int)(__ldg(r + 3) * 0.0625f);
    const int y2 = (int)(__ldg(r + 4) * 0.0625f);
    const int rh = y2 - y1 + 1;
    const int rw = x2 - x1 + 1;

    const int hs = min(max(y1 + (ph * rh) / POOLK, 0), HH);
    const int he = min(max(y1 + ((ph + 1) * rh + POOLK - 1) / POOLK, 0), HH);

    const int wid = threadIdx.x >> 5;
    const int lane = threadIdx.x & 31;

    if (wid < POOLK) {
        const int pw = wid;
        const int ws = min(max(x1 + (pw * rw) / POOLK, 0), WW);
        const int we = min(max(x1 + ((pw + 1) * rw + POOLK - 1) / POOLK, 0), WW);
        const int nh = he - hs;
        const int nw = we - ws;
        const int cnt = (nh > 0 && nw > 0) ? nh * nw : 0;
        float m = -INFINITY;
        for (int e = lane; e < cnt; e += 32) {
            const int dh = e / nw;
            const int dw = e - dh * nw;
            m = fmaxf(m, __ldg(g_fmax + (hs + dh) * WW + (ws + dw)));
        }
#pragma unroll
        for (int o = 16; o; o >>= 1)
            m = fmaxf(m, __shfl_xor_sync(0xffffffffu, m, o));

        // Fill this bin's 2 KB broadcast slice: 4 STS.128 per lane.
        float4* s4 = reinterpret_cast<float4*>(stile + pw * CC);
        const float4 vv = make_float4(m, m, m, m);
#pragma unroll
        for (int i = 0; i < 4; ++i)
            s4[lane + 32 * i] = vv;
    }
    __syncthreads();

    if (threadIdx.x == 0) {
        // Order generic-proxy smem writes before the async-proxy bulk read.
        asm volatile("fence.proxy.async.shared::cta;" ::: "memory");
        const float* gdst = out + (size_t)blockIdx.x * (POOLK * CC);
        const uint32_t ssrc = smem_u32(stile);
        asm volatile(
            "cp.async.bulk.global.shared::cta.bulk_group [%0], [%1], %2;"
            :: "l"(gdst), "r"(ssrc), "r"((int)(POOLK * CC * 4))
            : "memory");
        asm volatile("cp.async.bulk.commit_group;" ::: "memory");
        asm volatile("cp.async.bulk.wait_group 0;" ::: "memory");
    }
}

extern "C" void kernel_launch(void* const* d_in, const int* in_sizes, int n_in,
                              void* d_out, int out_size) {
    const float* rois = (const float*)d_in[0];
    const float* fm = (const float*)d_in[1];
    if (n_in >= 2 && in_sizes[0] > in_sizes[1]) {
        rois = (const float*)d_in[1];
        fm = (const float*)d_in[0];
    }
    float* out = (float*)d_out;

    fmax_kernel<<<(NPOS * 128) / 256, 256>>>(fm);      // 1250 blocks
    roi_kernel<<<NROIS * POOLK, 256>>>(rois, out);     // 2100 blocks
}